// round 10
// baseline (speedup 1.0000x reference)
#include <cuda_runtime.h>
#include <cuda_bf16.h>

// WaveletTransformLayer: x (B=128, T=2048, F=32) f32.
// Per (b,f): d1 (2047) | d2 (2044) | d3 (2037) | ma3 (2037), each / T.
//   m2[t] = 8*ma2[t] = x[t] + 2(x[t+1]+x[t+2]+x[t+3]) + x[t+4]
//   S[t]  = 64*ma3[t] = sum_{j=0..7} m2[t+j]
//   d1[t] = (x[t+1]-x[t])/2 ; d2[t] = (x[t+3]+x[t+4])/2 - m2[t]/8
//   d3[t] = m2[t+7]/8 - S[t]/64 ; ma3[t] = S[t]/64     (all x 1/T)
//
// R8: lane=f sliding-window compute. Input read directly from global
// (coalesced LDG.32, no input smem, ~2.4x read amplification vs 12x smem
// re-reads in R5). Outputs transposed via a 16.9KB staging buffer to keep
// stores coalesced. Warp = 8-t strip; block = 32-t chunk x 32 f; warp w
// stores segment w. Grid 1024 x 8 units each: balanced single wave.

#define T_LEN     2048
#define F_DIM     32
#define OUT_PER_F 8165
#define SEG1      2047
#define SEG2      4091
#define SEG3      6128
#define CHUNK     32
#define NCHUNK    64            // 2048 / 32
#define NUNITS    8192          // 128 b * 64 chunks
#define GRID      1024          // 8 units per block, balanced
#define SP        33            // staging pitch (floats)
#define SSEG      (CHUNK * SP)  // 1056 floats per segment buffer

__global__ __launch_bounds__(128, 8)
void wavelet_kernel(const float* __restrict__ x, float* __restrict__ out) {
    __shared__ float st[4 * SSEG];   // 4 * 1056 * 4B = 16896 B

    const int tid = threadIdx.x;
    const int w   = tid >> 5;        // warp 0..3 -> t-strip / store segment
    const int l   = tid & 31;        // lane: feature (compute), t (store)

    const int segoff = (w == 0) ? 0 : (w == 1) ? SEG1 : (w == 2) ? SEG2 : SEG3;
    const int lim    = (w == 0) ? 2047 : (w == 1) ? 2044 : 2037;

    const float inv   = 1.0f / 2048.0f;
    const float inv2  = inv * 0.5f;
    const float inv8  = inv * 0.125f;
    const float inv64 = inv * 0.015625f;

    const int  c    = blockIdx.x & (NCHUNK - 1);  // constant across iterations
    const int  T0   = c * CHUNK;
    const int  tb   = T0 + 8 * w;                 // this warp's t-strip base
    const bool last = (c == NCHUNK - 1);

    for (int u = blockIdx.x; u < NUNITS; u += GRID) {
        const int b = u >> 6;
        const float* base = x + (size_t)b * (T_LEN * F_DIM);

        // ---- Load 19-value window per lane (coalesced: 32 lanes = 32 consecutive f) ----
        float xv[19];
        if (!last) {
            const float* p = base + tb * F_DIM + l;
            #pragma unroll
            for (int j = 0; j < 19; ++j) xv[j] = p[F_DIM * j];
        } else {
            #pragma unroll
            for (int j = 0; j < 19; ++j) {
                int tt = tb + j; if (tt > T_LEN - 1) tt = T_LEN - 1;  // clamp; excess unused
                xv[j] = base[tt * F_DIM + l];
            }
        }

        // ---- FIR pyramid in registers ----
        float m2[15];
        #pragma unroll
        for (int i = 0; i < 15; ++i)
            m2[i] = (xv[i] + xv[i + 4]) + 2.0f * ((xv[i + 1] + xv[i + 2]) + xv[i + 3]);

        float S = ((m2[0] + m2[1]) + (m2[2] + m2[3]))
                + ((m2[4] + m2[5]) + (m2[6] + m2[7]));

        float* srow = st + (8 * w) * SP + l;   // stage[seg][tl][f=l]
        #pragma unroll
        for (int k = 0; k < 8; ++k) {
            float d1 = (xv[k + 1] - xv[k]) * inv2;
            float d2 = (xv[k + 3] + xv[k + 4]) * inv2 - m2[k] * inv8;
            float d3 = m2[k + 7] * inv8 - S * inv64;
            float m3 = S * inv64;
            srow[k * SP]            = d1;      // conflict-free: consecutive lanes/banks
            srow[k * SP + SSEG]     = d2;
            srow[k * SP + 2 * SSEG] = d3;
            srow[k * SP + 3 * SSEG] = m3;
            if (k < 7) S += m2[k + 8] - m2[k];
        }
        __syncthreads();

        // ---- Store: warp w -> segment w, lane = t, loop f (coalesced STG.32) ----
        const float* sp = st + w * SSEG + l * SP;   // stride-33 read: conflict-free
        float* op = out + (size_t)b * (F_DIM * OUT_PER_F) + segoff + T0 + l;
        if (!last) {
            #pragma unroll 8
            for (int f = 0; f < F_DIM; ++f) op[(size_t)f * OUT_PER_F] = sp[f];
        } else {
            if (T0 + l < lim) {
                #pragma unroll 8
                for (int f = 0; f < F_DIM; ++f) op[(size_t)f * OUT_PER_F] = sp[f];
            }
        }
        __syncthreads();   // protect staging reuse across units
    }
}

extern "C" void kernel_launch(void* const* d_in, const int* in_sizes, int n_in,
                              void* d_out, int out_size) {
    const float* x = (const float*)d_in[0];
    float* out = (float*)d_out;
    wavelet_kernel<<<GRID, 128>>>(x, out);
}

// round 11
// speedup vs baseline: 1.4499x; 1.4499x over previous
#include <cuda_runtime.h>
#include <cuda_bf16.h>

// WaveletTransformLayer: x (B=128, T=2048, F=32) f32.
// Per (b,f): d1 (2047) | d2 (2044) | d3 (2037) | ma3 (2037), each / T.
// Collapsed FIR taps over x[t..t+11]:
//   d1[t] = (x1-x0)/2 ; ma2 = [1,2,2,2,1]/8 ; ma3 = [1,3,5,7,8,8,8,8,7,5,3,1]/64
//   d2[t] = (x3+x4)/2 - ma2[t] ; d3[t] = ma2[t+7] - ma3[t]
//
// R11: R5 inner loop, new work geometry. Block = 512 threads = (t:128)x(fq:4),
// each thread 1t x 8f. 3 blocks/SM (48 warps, 75% occ cap), persistent
// GRID = 148*3 = 444 over 2048 units -> 4.61 units/block; per-SM totals are
// 13 or 14 units vs 13.84 avg => ~1% imbalance. This removes the straggler
// wave that pinned R5/R7 at ~49% achieved occupancy.

#define T_LEN   2048
#define F_DIM   32
#define TT      128
#define NTILES  (T_LEN / TT)     // 16
#define NUNITS  (NTILES * 128)   // 2048
#define HALO    12
#define LOADT   (TT + HALO)      // 140
#define PITCH   33               // conflict-free for STS.32 fill and LDS.32 compute
#define OUT_PER_F 8165
#define SEG1    2047
#define SEG2    4091
#define SEG3    6128
#define LIM1    2047
#define LIM2    2044
#define LIM3    2037

#define NSM     148
#define BLKSM   3
#define GRID    (NSM * BLKSM)    // 444
#define NTHR    512

__global__ __launch_bounds__(NTHR, BLKSM)
void wavelet_kernel(const float* __restrict__ x, float* __restrict__ out) {
    __shared__ float xs[LOADT * PITCH];   // 140*33*4 = 18480 B

    const int tid = threadIdx.x;          // 0..511
    const int t   = tid & 127;            // lane-contiguous t within warp
    const int fq  = tid >> 7;             // f-quarter 0..3 (8 features each)
    const int f0  = fq << 3;

    const float inv   = 1.0f / 2048.0f;
    const float inv2  = inv * 0.5f;
    const float inv8  = inv * 0.125f;
    const float inv64 = inv * 0.015625f;

    for (int u = blockIdx.x; u < NUNITS; u += GRID) {
        const int tile = u & (NTILES - 1);   // 0..15
        const int b    = u >> 4;             // 0..127
        const int t0   = tile * TT;

        // ---- Fill: LDG.128 (t-major, f contiguous) -> 4x STS.32, conflict-free ----
        const float4* gsrc = (const float4*)(x + (size_t)b * (T_LEN * F_DIM)
                                               + (size_t)t0 * F_DIM);
        if (tile != NTILES - 1) {
            #pragma unroll
            for (int k = 0; k < 3; ++k) {
                int i = tid + k * NTHR;
                if (i < LOADT * 8) {          // 1120 vec4s
                    int tt = i >> 3;
                    int f4 = (i & 7) << 2;
                    float4 v = gsrc[i];
                    float* d = &xs[tt * PITCH + f4];
                    d[0] = v.x; d[1] = v.y; d[2] = v.z; d[3] = v.w;
                }
            }
        } else {
            #pragma unroll
            for (int k = 0; k < 3; ++k) {
                int i = tid + k * NTHR;
                if (i < LOADT * 8) {
                    int tt = i >> 3;
                    int f4 = (i & 7) << 2;
                    float4 v = make_float4(0.f, 0.f, 0.f, 0.f);
                    if (t0 + tt < T_LEN) v = gsrc[i];
                    float* d = &xs[tt * PITCH + f4];
                    d[0] = v.x; d[1] = v.y; d[2] = v.z; d[3] = v.w;
                }
            }
        }
        __syncthreads();

        // ---- Compute: thread = t (lane-contiguous -> coalesced stores), 8 f each ----
        const int tg = t0 + t;
        float* outb = out + (size_t)b * (F_DIM * OUT_PER_F) + (size_t)f0 * OUT_PER_F;

        if (tile != NTILES - 1) {   // tiles 0..14: all stores unconditional
            #pragma unroll 2
            for (int fi = 0; fi < 8; ++fi) {
                const float* s = xs + t * PITCH + f0 + fi;
                float x0  = s[0 * PITCH],  x1 = s[1 * PITCH],  x2  = s[2 * PITCH];
                float x3  = s[3 * PITCH],  x4 = s[4 * PITCH],  x5  = s[5 * PITCH];
                float x6  = s[6 * PITCH],  x7 = s[7 * PITCH],  x8  = s[8 * PITCH];
                float x9  = s[9 * PITCH], x10 = s[10 * PITCH], x11 = s[11 * PITCH];

                float d1  = (x1 - x0) * inv2;
                float m2a = x0 + x4 + 2.0f * (x1 + x2 + x3);
                float d2  = (x3 + x4) * inv2 - m2a * inv8;
                float m2b = x7 + x11 + 2.0f * (x8 + x9 + x10);
                float m3  = (x0 + x11) + 3.0f * (x1 + x10) + 5.0f * (x2 + x9)
                          + 7.0f * (x3 + x8) + 8.0f * (x4 + x5 + x6 + x7);
                float d3  = m2b * inv8 - m3 * inv64;
                float ma3 = m3 * inv64;

                float* of = outb + (size_t)fi * OUT_PER_F;
                of[tg]        = d1;
                of[SEG1 + tg] = d2;
                of[SEG2 + tg] = d3;
                of[SEG3 + tg] = ma3;
            }
        } else {                    // tile 15: predicated stores
            const bool w1 = (tg < LIM1);
            const bool w2 = (tg < LIM2);
            const bool w3 = (tg < LIM3);
            #pragma unroll 2
            for (int fi = 0; fi < 8; ++fi) {
                const float* s = xs + t * PITCH + f0 + fi;
                float x0  = s[0 * PITCH],  x1 = s[1 * PITCH],  x2  = s[2 * PITCH];
                float x3  = s[3 * PITCH],  x4 = s[4 * PITCH],  x5  = s[5 * PITCH];
                float x6  = s[6 * PITCH],  x7 = s[7 * PITCH],  x8  = s[8 * PITCH];
                float x9  = s[9 * PITCH], x10 = s[10 * PITCH], x11 = s[11 * PITCH];

                float d1  = (x1 - x0) * inv2;
                float m2a = x0 + x4 + 2.0f * (x1 + x2 + x3);
                float d2  = (x3 + x4) * inv2 - m2a * inv8;
                float m2b = x7 + x11 + 2.0f * (x8 + x9 + x10);
                float m3  = (x0 + x11) + 3.0f * (x1 + x10) + 5.0f * (x2 + x9)
                          + 7.0f * (x3 + x8) + 8.0f * (x4 + x5 + x6 + x7);
                float d3  = m2b * inv8 - m3 * inv64;
                float ma3 = m3 * inv64;

                float* of = outb + (size_t)fi * OUT_PER_F;
                if (w1) of[tg]        = d1;
                if (w2) of[SEG1 + tg] = d2;
                if (w3) {
                    of[SEG2 + tg] = d3;
                    of[SEG3 + tg] = ma3;
                }
            }
        }
        __syncthreads();   // protect smem reuse across grid-stride iterations
    }
}

extern "C" void kernel_launch(void* const* d_in, const int* in_sizes, int n_in,
                              void* d_out, int out_size) {
    const float* x = (const float*)d_in[0];
    float* out = (float*)d_out;
    wavelet_kernel<<<GRID, NTHR>>>(x, out);
}